// round 8
// baseline (speedup 1.0000x reference)
#include <cuda_runtime.h>
#include <cuda_bf16.h>
#include <cstdint>

#define SEQ     512
#define NBATCH  256
#define NSTATE  1024
#define NOUT    256
#define ALPHA   0.1f
#define OMALPHA 0.9f

#define NCTA 128
#define NTHR 256
#define BM 32
#define BN 64

// smem strides in bf16 elems; 1032*2=2064B and 264*2=528B are 16 mod 128 -> conflict-free
#define WR_STR 1032
#define WO_STR 1032
#define TH_STR 264

#define SMEM_WR      (64 * WR_STR)
#define SMEM_WO      (16 * WO_STR)
#define SMEM_TH_HALF (32 * TH_STR)
#define SMEM_TH      (2 * SMEM_TH_HALF)
#define SMEM_RED     (8 * 512)
#define SMEM_BYTES   ((SMEM_WR + SMEM_WO + SMEM_TH) * 2 + SMEM_RED * 4 + 16)

__device__ __align__(16) __nv_bfloat16 g_th[2][NBATCH * NSTATE];
__device__ unsigned g_flags[NCTA * 32];   // padded: one flag per 128B

__device__ __forceinline__ float tanh_f(float v) {
    float r; asm("tanh.approx.f32 %0, %1;" : "=f"(r) : "f"(v)); return r;
}
__device__ __forceinline__ unsigned pack2(float a, float b) {
    __nv_bfloat162 t = __floats2bfloat162_rn(a, b);
    return *reinterpret_cast<unsigned*>(&t);
}
__device__ __forceinline__ unsigned ldcg_u32(const void* p) {
    unsigned v; asm volatile("ld.global.cg.b32 %0, [%1];" : "=r"(v) : "l"(p)); return v;
}
__device__ __forceinline__ void stcg_u32(void* p, unsigned v) {
    asm volatile("st.global.cg.b32 [%0], %1;" :: "l"(p), "r"(v));
}
__device__ __forceinline__ void cp_async16(void* smem_dst, const void* gsrc) {
    unsigned s = (unsigned)__cvta_generic_to_shared(smem_dst);
    asm volatile("cp.async.cg.shared.global [%0], [%1], 16;" :: "r"(s), "l"(gsrc));
}
__device__ __forceinline__ void mma16816(float c[4], const unsigned a[4], const unsigned b[2]) {
    asm volatile(
        "mma.sync.aligned.m16n8k16.row.col.f32.bf16.bf16.f32 "
        "{%0,%1,%2,%3},{%4,%5,%6,%7},{%8,%9},{%0,%1,%2,%3};"
        : "+f"(c[0]), "+f"(c[1]), "+f"(c[2]), "+f"(c[3])
        : "r"(a[0]), "r"(a[1]), "r"(a[2]), "r"(a[3]), "r"(b[0]), "r"(b[1]));
}

// Grid barrier on monotone per-CTA counters (replay-safe).
__device__ __forceinline__ void gbar(int cta, unsigned target) {
    __syncthreads();
    __threadfence();
    if (threadIdx.x == 0)
        asm volatile("st.release.gpu.global.b32 [%0], %1;"
                     :: "l"(g_flags + cta * 32), "r"(target) : "memory");
    if (threadIdx.x < NCTA) {
        unsigned v;
        do {
            asm volatile("ld.acquire.gpu.global.b32 %0, [%1];"
                         : "=r"(v) : "l"(g_flags + threadIdx.x * 32) : "memory");
        } while (v < target);
    }
    __syncthreads();
}

__global__ void __launch_bounds__(NTHR, 1)
rnn_scan_kernel(const float* __restrict__ x, const float* __restrict__ h_init,
                const float* __restrict__ w_r, const float* __restrict__ b_r,
                const float* __restrict__ w_o, const float* __restrict__ b_o,
                float* __restrict__ out)
{
    extern __shared__ char smem_raw[];
    __nv_bfloat16* wr_s = (__nv_bfloat16*)smem_raw;
    __nv_bfloat16* wo_s = wr_s + SMEM_WR;
    __nv_bfloat16* th_s = wo_s + SMEM_WO;
    float*         red  = (float*)(th_s + SMEM_TH);
    unsigned*      s_base = (unsigned*)(red + SMEM_RED);

    const int cta = blockIdx.x, tid = threadIdx.x;
    const int wid = tid >> 5, lane = tid & 31;
    const int g = lane >> 2, tg = lane & 3;

    // GEMM1 tile: 8(M) x 16(N) CTA grid; warps 2(M) x 4(N); warp tile m16n16
    const int row0 = (cta >> 4) * BM;
    const int col0 = (cta & 15) * BN;
    const int wm = (wid >> 2) * 16, wn = (wid & 3) * 16;
    const int r0 = row0 + wm + g, r1 = r0 + 8;
    const int cb = col0 + wn + 2 * tg;

    // GEMM2 tile: 8(M) x 16(N) CTA grid; 32x16 tile; warps K-split (128 each)
    const int mb2 = (cta & 7) * 32;
    const int nb2 = (cta >> 3) * 16;
    const int kw  = wid * 128;

    // ---- prologue: stage weights (once for all 512 steps) ----
    for (int i = tid; i < 64 * 256; i += NTHR) {
        int n = i >> 8, c4 = i & 255;
        float4 v = ((const float4*)(w_r + (col0 + n) * NSTATE))[c4];
        __nv_bfloat16* d = wr_s + n * WR_STR + c4 * 4;
        d[0] = __float2bfloat16(v.x); d[1] = __float2bfloat16(v.y);
        d[2] = __float2bfloat16(v.z); d[3] = __float2bfloat16(v.w);
    }
    for (int i = tid; i < 16 * 256; i += NTHR) {
        int n = i >> 8, c4 = i & 255;
        float4 v = ((const float4*)(w_o + (nb2 + n) * NSTATE))[c4];
        __nv_bfloat16* d = wo_s + n * WO_STR + c4 * 4;
        d[0] = __float2bfloat16(v.x); d[1] = __float2bfloat16(v.y);
        d[2] = __float2bfloat16(v.z); d[3] = __float2bfloat16(v.w);
    }

    float br[4] = { b_r[cb], b_r[cb + 1], b_r[cb + 8], b_r[cb + 9] };
    float h[8];
    h[0] = h_init[r0 * NSTATE + cb];     h[1] = h_init[r0 * NSTATE + cb + 1];
    h[2] = h_init[r1 * NSTATE + cb];     h[3] = h_init[r1 * NSTATE + cb + 1];
    h[4] = h_init[r0 * NSTATE + cb + 8]; h[5] = h_init[r0 * NSTATE + cb + 9];
    h[6] = h_init[r1 * NSTATE + cb + 8]; h[7] = h_init[r1 * NSTATE + cb + 9];

    stcg_u32(&g_th[0][r0 * NSTATE + cb],     pack2(tanh_f(h[0]), tanh_f(h[1])));
    stcg_u32(&g_th[0][r1 * NSTATE + cb],     pack2(tanh_f(h[2]), tanh_f(h[3])));
    stcg_u32(&g_th[0][r0 * NSTATE + cb + 8], pack2(tanh_f(h[4]), tanh_f(h[5])));
    stcg_u32(&g_th[0][r1 * NSTATE + cb + 8], pack2(tanh_f(h[6]), tanh_f(h[7])));

    if (tid == 0) *s_base = g_flags[cta * 32];
    __syncthreads();
    const unsigned base = *s_base;
    unsigned bar = 1;
    gbar(cta, base + bar); bar++;

    // ---- scan ----
    for (int t = 0; t < SEQ; t++) {
        const int pc = t & 1, pn = pc ^ 1;
        const __nv_bfloat16* thc = g_th[pc];

        // phase A: P = tanh(h) @ w_r^T tile
        float C0[4] = {0,0,0,0}, C1[4] = {0,0,0,0};
        for (int i = tid; i < 1024; i += NTHR) {
            int r = i >> 5, c8 = (i & 31) * 8;
            cp_async16(th_s + r * TH_STR + c8, thc + (row0 + r) * NSTATE + c8);
        }
        asm volatile("cp.async.commit_group;");

        for (int ch = 0; ch < 4; ch++) {
            __nv_bfloat16* cur = th_s + (ch & 1) * SMEM_TH_HALF;
            if (ch < 3) {
                __nv_bfloat16* nxt = th_s + ((ch + 1) & 1) * SMEM_TH_HALF;
                const int kb2 = (ch + 1) * 256;
                for (int i = tid; i < 1024; i += NTHR) {
                    int r = i >> 5, c8 = (i & 31) * 8;
                    cp_async16(nxt + r * TH_STR + c8, thc + (row0 + r) * NSTATE + kb2 + c8);
                }
                asm volatile("cp.async.commit_group;");
                asm volatile("cp.async.wait_group 1;");
            } else {
                asm volatile("cp.async.wait_group 0;");
            }
            __syncthreads();

            const int kb = ch * 256;
            #pragma unroll
            for (int kk = 0; kk < 16; kk++) {
                unsigned a[4], b0[2], b1[2];
                const __nv_bfloat16* ap = cur + (wm + g) * TH_STR + kk * 16 + 2 * tg;
                a[0] = *(const unsigned*)ap;
                a[1] = *(const unsigned*)(ap + 8 * TH_STR);
                a[2] = *(const unsigned*)(ap + 8);
                a[3] = *(const unsigned*)(ap + 8 * TH_STR + 8);
                const __nv_bfloat16* bp = wr_s + (wn + g) * WR_STR + kb + kk * 16 + 2 * tg;
                b0[0] = *(const unsigned*)bp;
                b0[1] = *(const unsigned*)(bp + 8);
                b1[0] = *(const unsigned*)(bp + 8 * WR_STR);
                b1[1] = *(const unsigned*)(bp + 8 * WR_STR + 8);
                mma16816(C0, a, b0);
                mma16816(C1, a, b1);
            }
            __syncthreads();
        }

        #pragma unroll
        for (int j = 0; j < 4; j++) {
            h[j]     = OMALPHA * h[j]     + ALPHA * (C0[j] + br[j & 1]);
            h[4 + j] = OMALPHA * h[4 + j] + ALPHA * (C1[j] + br[2 + (j & 1)]);
        }
        {
            __nv_bfloat16* thw = g_th[pn];
            stcg_u32(&thw[r0 * NSTATE + cb],     pack2(tanh_f(h[0]), tanh_f(h[1])));
            stcg_u32(&thw[r1 * NSTATE + cb],     pack2(tanh_f(h[2]), tanh_f(h[3])));
            stcg_u32(&thw[r0 * NSTATE + cb + 8], pack2(tanh_f(h[4]), tanh_f(h[5])));
            stcg_u32(&thw[r1 * NSTATE + cb + 8], pack2(tanh_f(h[6]), tanh_f(h[7])));
        }

        gbar(cta, base + bar); bar++;   // only barrier in the step

        // phase B: err = tanh(h_new) @ w_o^T + b_o - x_t
        const __nv_bfloat16* thn = g_th[pn];
        float D[4][4];
        #pragma unroll
        for (int q = 0; q < 4; q++) { D[q][0]=0; D[q][1]=0; D[q][2]=0; D[q][3]=0; }

        #pragma unroll 4
        for (int kk = 0; kk < 8; kk++) {
            const int k = kw + kk * 16;
            unsigned a0[4], a1[4], b0[2], b1[2];
            const __nv_bfloat16* ap = thn + (mb2 + g) * NSTATE + k + 2 * tg;
            a0[0] = ldcg_u32(ap);
            a0[1] = ldcg_u32(ap + 8 * NSTATE);
            a0[2] = ldcg_u32(ap + 8);
            a0[3] = ldcg_u32(ap + 8 * NSTATE + 8);
            const __nv_bfloat16* ap1 = ap + 16 * NSTATE;
            a1[0] = ldcg_u32(ap1);
            a1[1] = ldcg_u32(ap1 + 8 * NSTATE);
            a1[2] = ldcg_u32(ap1 + 8);
            a1[3] = ldcg_u32(ap1 + 8 * NSTATE + 8);
            const __nv_bfloat16* bp = wo_s + g * WO_STR + k + 2 * tg;
            b0[0] = *(const unsigned*)bp;
            b0[1] = *(const unsigned*)(bp + 8);
            b1[0] = *(const unsigned*)(bp + 8 * WO_STR);
            b1[1] = *(const unsigned*)(bp + 8 * WO_STR + 8);
            mma16816(D[0], a0, b0);
            mma16816(D[1], a0, b1);
            mma16816(D[2], a1, b0);
            mma16816(D[3], a1, b1);
        }

        {
            float* rw = red + wid * 512;
            #pragma unroll
            for (int q = 0; q < 4; q++) {
                int mi = q >> 1, ni = q & 1;
                #pragma unroll
                for (int j = 0; j < 4; j++) {
                    int rl = mi * 16 + g + ((j >> 1) << 3);
                    int cl = ni * 8 + 2 * tg + (j & 1);
                    rw[rl * 16 + cl] = D[q][j];
                }
            }
        }
        __syncthreads();
        for (int i = tid; i < 512; i += NTHR) {
            float s = red[i]        + red[512 + i]  + red[1024 + i] + red[1536 + i]
                    + red[2048 + i] + red[2560 + i] + red[3072 + i] + red[3584 + i];
            int r = i >> 4, c = i & 15;
            int oidx = (t * NBATCH + (mb2 + r)) * NOUT + (nb2 + c);
            out[oidx] = s + b_o[nb2 + c] - x[oidx];
        }
        __syncthreads();
    }
}

extern "C" void kernel_launch(void* const* d_in, const int* in_sizes, int n_in,
                              void* d_out, int out_size) {
    const float* x      = (const float*)d_in[0];
    const float* h_init = (const float*)d_in[1];
    const float* w_r    = (const float*)d_in[2];
    const float* b_r    = (const float*)d_in[3];
    const float* w_o    = (const float*)d_in[4];
    const float* b_o    = (const float*)d_in[5];
    float* out = (float*)d_out;

    static bool configured = false;
    if (!configured) {
        cudaFuncSetAttribute(rnn_scan_kernel,
                             cudaFuncAttributeMaxDynamicSharedMemorySize, SMEM_BYTES);
        configured = true;
    }
    rnn_scan_kernel<<<NCTA, NTHR, SMEM_BYTES>>>(x, h_init, w_r, b_r, w_o, b_o, out);
}

// round 9
// speedup vs baseline: 1.2277x; 1.2277x over previous
#include <cuda_runtime.h>
#include <cuda_bf16.h>
#include <cstdint>

#define SEQ     512
#define NBATCH  256
#define NSTATE  1024
#define NOUT    256
#define ALPHA   0.1f
#define OMALPHA 0.9f

#define NCTA 128
#define NTHR 256
#define BM 32
#define BN 64

// smem strides in bf16 elems; stride*2 mod 128 = 16 -> conflict-free LDSM/LDS
#define WR_STR 1032
#define WO_STR 1032
#define TH_STR 264

#define SMEM_WR      (64 * WR_STR)
#define SMEM_WO      (16 * WO_STR)
#define SMEM_TH_HALF (32 * TH_STR)
#define SMEM_TH      (2 * SMEM_TH_HALF)
#define SMEM_RED     (8 * 512)
#define SMEM_BYTES   ((SMEM_WR + SMEM_WO + SMEM_TH) * 2 + SMEM_RED * 4 + 16)
#define HALF_B       (SMEM_TH_HALF * 2)   // bytes per th half-buffer

__device__ __align__(16) __nv_bfloat16 g_th[2][NBATCH * NSTATE];
__device__ unsigned g_flags[NCTA * 32];   // one flag per 128B

__device__ __forceinline__ float tanh_f(float v) {
    float r; asm("tanh.approx.f32 %0, %1;" : "=f"(r) : "f"(v)); return r;
}
__device__ __forceinline__ unsigned pack2(float a, float b) {
    __nv_bfloat162 t = __floats2bfloat162_rn(a, b);
    return *reinterpret_cast<unsigned*>(&t);
}
__device__ __forceinline__ void stcg_u32(void* p, unsigned v) {
    asm volatile("st.global.cg.b32 [%0], %1;" :: "l"(p), "r"(v));
}
__device__ __forceinline__ void cp_async16(void* smem_dst, const void* gsrc) {
    unsigned s = (unsigned)__cvta_generic_to_shared(smem_dst);
    asm volatile("cp.async.cg.shared.global [%0], [%1], 16;" :: "r"(s), "l"(gsrc));
}
__device__ __forceinline__ void ldsm4(unsigned r[4], unsigned addr) {
    asm volatile("ldmatrix.sync.aligned.m8n8.x4.shared.b16 {%0,%1,%2,%3}, [%4];"
                 : "=r"(r[0]), "=r"(r[1]), "=r"(r[2]), "=r"(r[3]) : "r"(addr));
}
__device__ __forceinline__ void mma16816(float c[4], const unsigned a[4], const unsigned b[2]) {
    asm volatile(
        "mma.sync.aligned.m16n8k16.row.col.f32.bf16.bf16.f32 "
        "{%0,%1,%2,%3},{%4,%5,%6,%7},{%8,%9},{%0,%1,%2,%3};"
        : "+f"(c[0]), "+f"(c[1]), "+f"(c[2]), "+f"(c[3])
        : "r"(a[0]), "r"(a[1]), "r"(a[2]), "r"(a[3]), "r"(b[0]), "r"(b[1]));
}

// 16-CTA group barrier on monotone per-CTA counters (replay-safe).
__device__ __forceinline__ void gbar(int cta, int grp, unsigned target) {
    __syncthreads();
    __threadfence();
    if (threadIdx.x == 0)
        asm volatile("st.release.gpu.global.b32 [%0], %1;"
                     :: "l"(g_flags + cta * 32), "r"(target) : "memory");
    if (threadIdx.x < 16) {
        unsigned v;
        const unsigned* f = g_flags + (grp * 16 + threadIdx.x) * 32;
        do {
            asm volatile("ld.acquire.gpu.global.b32 %0, [%1];"
                         : "=r"(v) : "l"(f) : "memory");
        } while (v < target);
    }
    __syncthreads();
}

__global__ void __launch_bounds__(NTHR, 1)
rnn_scan_kernel(const float* __restrict__ x, const float* __restrict__ h_init,
                const float* __restrict__ w_r, const float* __restrict__ b_r,
                const float* __restrict__ w_o, const float* __restrict__ b_o,
                float* __restrict__ out)
{
    extern __shared__ char smem_raw[];
    __nv_bfloat16* wr_s = (__nv_bfloat16*)smem_raw;
    __nv_bfloat16* wo_s = wr_s + SMEM_WR;
    __nv_bfloat16* th_s = wo_s + SMEM_WO;
    float*         red  = (float*)(th_s + SMEM_TH);
    unsigned*      s_base = (unsigned*)(red + SMEM_RED);

    const int cta = blockIdx.x, tid = threadIdx.x;
    const int wid = tid >> 5, lane = tid & 31;
    const int g = lane >> 2, tg = lane & 3;
    const int grp = cta >> 4;                 // 16 CTAs per independent group

    // GEMM1 tile: group = M-block, (cta&15) = N-block; warps 2(M) x 4(N), m16n16 each
    const int row0 = grp * BM;
    const int col0 = (cta & 15) * BN;
    const int wm = (wid >> 2) * 16, wn = (wid & 3) * 16;
    const int r0 = row0 + wm + g, r1 = r0 + 8;
    const int cb = col0 + wn + 2 * tg;

    // GEMM2 tile: same rows as phase A (keeps group closed); cols (cta&15)*16; warps K-split
    const int nb2 = (cta & 15) * 16;

    const unsigned th_u32 = (unsigned)__cvta_generic_to_shared(th_s);
    const unsigned wr_u32 = (unsigned)__cvta_generic_to_shared(wr_s);
    const unsigned wo_u32 = (unsigned)__cvta_generic_to_shared(wo_s);
    const int l15 = lane & 15, lhi = lane >> 4;
    const unsigned aA_off = ((wm + l15) * TH_STR + lhi * 8) * 2;   // phase A A-frag
    const unsigned bA_off = ((wn + l15) * WR_STR + lhi * 8) * 2;   // phase A B-frag
    const unsigned aB_off = (l15 * TH_STR + lhi * 8) * 2;          // phase B A-frag
    const unsigned bB_off = (l15 * WO_STR + lhi * 8) * 2;          // phase B B-frag

    // ---- prologue: stage weights once ----
    for (int i = tid; i < 64 * 256; i += NTHR) {
        int n = i >> 8, c4 = i & 255;
        float4 v = ((const float4*)(w_r + (col0 + n) * NSTATE))[c4];
        __nv_bfloat16* d = wr_s + n * WR_STR + c4 * 4;
        d[0] = __float2bfloat16(v.x); d[1] = __float2bfloat16(v.y);
        d[2] = __float2bfloat16(v.z); d[3] = __float2bfloat16(v.w);
    }
    for (int i = tid; i < 16 * 256; i += NTHR) {
        int n = i >> 8, c4 = i & 255;
        float4 v = ((const float4*)(w_o + (nb2 + n) * NSTATE))[c4];
        __nv_bfloat16* d = wo_s + n * WO_STR + c4 * 4;
        d[0] = __float2bfloat16(v.x); d[1] = __float2bfloat16(v.y);
        d[2] = __float2bfloat16(v.z); d[3] = __float2bfloat16(v.w);
    }

    float br[4] = { b_r[cb], b_r[cb + 1], b_r[cb + 8], b_r[cb + 9] };
    float h[8];
    h[0] = h_init[r0 * NSTATE + cb];     h[1] = h_init[r0 * NSTATE + cb + 1];
    h[2] = h_init[r1 * NSTATE + cb];     h[3] = h_init[r1 * NSTATE + cb + 1];
    h[4] = h_init[r0 * NSTATE + cb + 8]; h[5] = h_init[r0 * NSTATE + cb + 9];
    h[6] = h_init[r1 * NSTATE + cb + 8]; h[7] = h_init[r1 * NSTATE + cb + 9];

    stcg_u32(&g_th[0][r0 * NSTATE + cb],     pack2(tanh_f(h[0]), tanh_f(h[1])));
    stcg_u32(&g_th[0][r1 * NSTATE + cb],     pack2(tanh_f(h[2]), tanh_f(h[3])));
    stcg_u32(&g_th[0][r0 * NSTATE + cb + 8], pack2(tanh_f(h[4]), tanh_f(h[5])));
    stcg_u32(&g_th[0][r1 * NSTATE + cb + 8], pack2(tanh_f(h[6]), tanh_f(h[7])));

    if (tid == 0) *s_base = g_flags[cta * 32];
    __syncthreads();
    const unsigned base = *s_base;
    unsigned bar = 1;
    gbar(cta, grp, base + bar); bar++;

    // ---- scan ----
    for (int t = 0; t < SEQ; t++) {
        const int pc = t & 1, pn = pc ^ 1;
        const __nv_bfloat16* thc = g_th[pc];

        // ===== phase A: P = tanh(h) @ w_r^T (32x64 tile, K=1024 in 4 chunks) =====
        float C0[4] = {0,0,0,0}, C1[4] = {0,0,0,0};
        for (int i = tid; i < 1024; i += NTHR) {
            int r = i >> 5, c8 = (i & 31) * 8;
            cp_async16(th_s + r * TH_STR + c8, thc + (row0 + r) * NSTATE + c8);
        }
        asm volatile("cp.async.commit_group;");

        for (int ch = 0; ch < 4; ch++) {
            asm volatile("cp.async.wait_group 0;");
            __syncthreads();
            if (ch < 3) {
                __nv_bfloat16* nxt = th_s + ((ch + 1) & 1) * SMEM_TH_HALF;
                const int kb2 = (ch + 1) * 256;
                for (int i = tid; i < 1024; i += NTHR) {
                    int r = i >> 5, c8 = (i & 31) * 8;
                    cp_async16(nxt + r * TH_STR + c8, thc + (row0 + r) * NSTATE + kb2 + c8);
                }
                asm volatile("cp.async.commit_group;");
            }
            const unsigned cur = th_u32 + (ch & 1) * HALF_B;
            const unsigned abase = cur + aA_off;
            const unsigned bbase = wr_u32 + bA_off + ch * 512;  // 256 cols * 2B
            #pragma unroll
            for (int kk = 0; kk < 16; kk++) {
                unsigned a[4], b[4];
                ldsm4(a, abase + kk * 32);
                ldsm4(b, bbase + kk * 32);
                unsigned b0[2] = { b[0], b[2] }, b1[2] = { b[1], b[3] };
                mma16816(C0, a, b0);
                mma16816(C1, a, b1);
            }
        }

        // h update + publish tanh(h_new)
        #pragma unroll
        for (int j = 0; j < 4; j++) {
            h[j]     = OMALPHA * h[j]     + ALPHA * (C0[j] + br[j & 1]);
            h[4 + j] = OMALPHA * h[4 + j] + ALPHA * (C1[j] + br[2 + (j & 1)]);
        }
        {
            __nv_bfloat16* thw = g_th[pn];
            stcg_u32(&thw[r0 * NSTATE + cb],     pack2(tanh_f(h[0]), tanh_f(h[1])));
            stcg_u32(&thw[r1 * NSTATE + cb],     pack2(tanh_f(h[2]), tanh_f(h[3])));
            stcg_u32(&thw[r0 * NSTATE + cb + 8], pack2(tanh_f(h[4]), tanh_f(h[5])));
            stcg_u32(&thw[r1 * NSTATE + cb + 8], pack2(tanh_f(h[6]), tanh_f(h[7])));
        }

        gbar(cta, grp, base + bar); bar++;   // only inter-CTA sync in the step

        // ===== phase B: err = tanh(h_new) @ w_o^T + b_o - x_t (32x16 tile) =====
        const __nv_bfloat16* thn = g_th[pn];
        float D[4][4];
        #pragma unroll
        for (int q = 0; q < 4; q++) { D[q][0]=0; D[q][1]=0; D[q][2]=0; D[q][3]=0; }

        for (int i = tid; i < 1024; i += NTHR) {
            int r = i >> 5, c8 = (i & 31) * 8;
            cp_async16(th_s + r * TH_STR + c8, thn + (row0 + r) * NSTATE + c8);
        }
        asm volatile("cp.async.commit_group;");

        const int kl0 = wid * 32;   // warp K-split within each 256-chunk
        for (int ch = 0; ch < 4; ch++) {
            asm volatile("cp.async.wait_group 0;");
            __syncthreads();
            if (ch < 3) {
                __nv_bfloat16* nxt = th_s + ((ch + 1) & 1) * SMEM_TH_HALF;
                const int kb2 = (ch + 1) * 256;
                for (int i = tid; i < 1024; i += NTHR) {
                    int r = i >> 5, c8 = (i & 31) * 8;
                    cp_async16(nxt + r * TH_STR + c8, thn + (row0 + r) * NSTATE + kb2 + c8);
                }
                asm volatile("cp.async.commit_group;");
            }
            const unsigned cur = th_u32 + (ch & 1) * HALF_B;
            #pragma unroll
            for (int kk = 0; kk < 2; kk++) {
                const int kl = kl0 + kk * 16;
                unsigned a0[4], a1[4], b[4];
                ldsm4(a0, cur + aB_off + kl * 2);
                ldsm4(a1, cur + aB_off + kl * 2 + 16 * TH_STR * 2);
                ldsm4(b, wo_u32 + bB_off + (ch * 256 + kl) * 2);
                unsigned b0[2] = { b[0], b[2] }, b1[2] = { b[1], b[3] };
                mma16816(D[0], a0, b0);
                mma16816(D[1], a0, b1);
                mma16816(D[2], a1, b0);
                mma16816(D[3], a1, b1);
            }
        }

        // cross-warp K reduction + fused epilogue
        {
            float* rw = red + wid * 512;
            #pragma unroll
            for (int q = 0; q < 4; q++) {
                int mi = q >> 1, ni = q & 1;
                #pragma unroll
                for (int j = 0; j < 4; j++) {
                    int rl = mi * 16 + g + ((j >> 1) << 3);
                    int cl = ni * 8 + 2 * tg + (j & 1);
                    rw[rl * 16 + cl] = D[q][j];
                }
            }
        }
        __syncthreads();
        for (int i = tid; i < 512; i += NTHR) {
            float s = red[i]        + red[512 + i]  + red[1024 + i] + red[1536 + i]
                    + red[2048 + i] + red[2560 + i] + red[3072 + i] + red[3584 + i];
            int r = i >> 4, c = i & 15;
            int oidx = (t * NBATCH + (row0 + r)) * NOUT + (nb2 + c);
            out[oidx] = s + b_o[nb2 + c] - x[oidx];
        }
        __syncthreads();
    }
}

extern "C" void kernel_launch(void* const* d_in, const int* in_sizes, int n_in,
                              void* d_out, int out_size) {
    const float* x      = (const float*)d_in[0];
    const float* h_init = (const float*)d_in[1];
    const float* w_r    = (const float*)d_in[2];
    const float* b_r    = (const float*)d_in[3];
    const float* w_o    = (const float*)d_in[4];
    const float* b_o    = (const float*)d_in[5];
    float* out = (float*)d_out;

    static bool configured = false;
    if (!configured) {
        cudaFuncSetAttribute(rnn_scan_kernel,
                             cudaFuncAttributeMaxDynamicSharedMemorySize, SMEM_BYTES);
        configured = true;
    }
    rnn_scan_kernel<<<NCTA, NTHR, SMEM_BYTES>>>(x, h_init, w_r, b_r, w_o, b_o, out);
}

// round 10
// speedup vs baseline: 1.3644x; 1.1113x over previous
#include <cuda_runtime.h>
#include <cuda_bf16.h>
#include <cstdint>

#define SEQ     512
#define NBATCH  256
#define NSTATE  1024
#define NOUT    256
#define ALPHA   0.1f
#define OMALPHA 0.9f

#define NCTA 128
#define NTHR 256
#define BM 32
#define BN 64

// smem strides in bf16 elems; stride*2 mod 128 = 16 -> conflict-free LDSM
#define WR_STR 1032
#define WO_STR 1032
#define TH_STR 264

#define SMEM_WR      (64 * WR_STR)
#define SMEM_WO      (16 * WO_STR)
#define SMEM_TH_HALF (32 * TH_STR)
#define SMEM_TH      (2 * SMEM_TH_HALF)
#define SMEM_RED     (8 * 512)
#define SMEM_BYTES   ((SMEM_WR + SMEM_WO + SMEM_TH) * 2 + SMEM_RED * 4 + 64)
#define HALF_B       (SMEM_TH_HALF * 2)      // bytes per th half-buffer
#define CHUNK_BYTES  16384                   // 32 rows x 512 B

__device__ __align__(16) __nv_bfloat16 g_th[2][NBATCH * NSTATE];
__device__ unsigned g_flags[NCTA * 32];      // one flag per 128B

__device__ __forceinline__ float tanh_f(float v) {
    float r; asm("tanh.approx.f32 %0, %1;" : "=f"(r) : "f"(v)); return r;
}
__device__ __forceinline__ unsigned pack2(float a, float b) {
    __nv_bfloat162 t = __floats2bfloat162_rn(a, b);
    return *reinterpret_cast<unsigned*>(&t);
}
__device__ __forceinline__ void stcg_u32(void* p, unsigned v) {
    asm volatile("st.global.cg.b32 [%0], %1;" :: "l"(p), "r"(v));
}
__device__ __forceinline__ void ldsm4(unsigned r[4], unsigned addr) {
    asm volatile("ldmatrix.sync.aligned.m8n8.x4.shared.b16 {%0,%1,%2,%3}, [%4];"
                 : "=r"(r[0]), "=r"(r[1]), "=r"(r[2]), "=r"(r[3]) : "r"(addr));
}
__device__ __forceinline__ void mma16816(float c[4], const unsigned a[4], const unsigned b[2]) {
    asm volatile(
        "mma.sync.aligned.m16n8k16.row.col.f32.bf16.bf16.f32 "
        "{%0,%1,%2,%3},{%4,%5,%6,%7},{%8,%9},{%0,%1,%2,%3};"
        : "+f"(c[0]), "+f"(c[1]), "+f"(c[2]), "+f"(c[3])
        : "r"(a[0]), "r"(a[1]), "r"(a[2]), "r"(a[3]), "r"(b[0]), "r"(b[1]));
}

// ---- mbarrier + 1D TMA bulk ----
__device__ __forceinline__ void mbar_init(unsigned mbar, unsigned count) {
    asm volatile("mbarrier.init.shared.b64 [%0], %1;" :: "r"(mbar), "r"(count));
}
__device__ __forceinline__ void mbar_expect_tx(unsigned mbar, unsigned bytes) {
    asm volatile("mbarrier.arrive.expect_tx.shared.b64 _, [%0], %1;"
                 :: "r"(mbar), "r"(bytes) : "memory");
}
__device__ __forceinline__ void mbar_wait(unsigned mbar, unsigned parity) {
    asm volatile(
        "{\n\t.reg .pred P1;\n\t"
        "LAB_W_%=:\n\t"
        "mbarrier.try_wait.parity.acquire.cta.shared::cta.b64 P1, [%0], %1, 0x989680;\n\t"
        "@P1 bra LAB_D_%=;\n\t"
        "bra LAB_W_%=;\n\t"
        "LAB_D_%=:\n\t}"
        :: "r"(mbar), "r"(parity) : "memory");
}
__device__ __forceinline__ void bulk_ldg(unsigned dst_smem, const void* src,
                                         unsigned bytes, unsigned mbar) {
    asm volatile(
        "cp.async.bulk.shared::cta.global.mbarrier::complete_tx::bytes [%0], [%1], %2, [%3];"
        :: "r"(dst_smem), "l"(src), "r"(bytes), "r"(mbar) : "memory");
}

// 16-CTA group barrier on monotone per-CTA counters (replay-safe).
__device__ __forceinline__ void gbar(int cta, int grp, unsigned target) {
    __syncthreads();
    __threadfence();
    if (threadIdx.x == 0)
        asm volatile("st.release.gpu.global.b32 [%0], %1;"
                     :: "l"(g_flags + cta * 32), "r"(target) : "memory");
    if (threadIdx.x < 16) {
        unsigned v;
        const unsigned* f = g_flags + (grp * 16 + threadIdx.x) * 32;
        do {
            asm volatile("ld.acquire.gpu.global.b32 %0, [%1];"
                         : "=r"(v) : "l"(f) : "memory");
        } while (v < target);
    }
    __syncthreads();
}

__global__ void __launch_bounds__(NTHR, 1)
rnn_scan_kernel(const float* __restrict__ x, const float* __restrict__ h_init,
                const float* __restrict__ w_r, const float* __restrict__ b_r,
                const float* __restrict__ w_o, const float* __restrict__ b_o,
                float* __restrict__ out)
{
    extern __shared__ char smem_raw[];
    __nv_bfloat16* wr_s = (__nv_bfloat16*)smem_raw;
    __nv_bfloat16* wo_s = wr_s + SMEM_WR;
    __nv_bfloat16* th_s = wo_s + SMEM_WO;
    float*         red  = (float*)(th_s + SMEM_TH);
    unsigned long long* mbars = (unsigned long long*)(red + SMEM_RED);  // 2 mbarriers
    unsigned*      s_base = (unsigned*)(mbars + 2);

    const int cta = blockIdx.x, tid = threadIdx.x;
    const int wid = tid >> 5, lane = tid & 31;
    const int g = lane >> 2, tg = lane & 3;
    const int grp = cta >> 4;

    // tile coords: group = 32-row batch block; (cta&15) = 64-col state block
    const int row0 = grp * BM;
    const int col0 = (cta & 15) * BN;
    const int wm = (wid >> 2) * 16, wn = (wid & 3) * 16;
    const int r0 = row0 + wm + g, r1 = r0 + 8;
    const int cb = col0 + wn + 2 * tg;
    const int nb2 = (cta & 15) * 16;          // D-tile output cols

    const unsigned th_u32 = (unsigned)__cvta_generic_to_shared(th_s);
    const unsigned wr_u32 = (unsigned)__cvta_generic_to_shared(wr_s);
    const unsigned wo_u32 = (unsigned)__cvta_generic_to_shared(wo_s);
    const unsigned mb_u32 = (unsigned)__cvta_generic_to_shared(mbars);
    const int l15 = lane & 15, lhi = lane >> 4;
    const unsigned aA_off = ((wm + l15) * TH_STR + lhi * 8) * 2;
    const unsigned bA_off = ((wn + l15) * WR_STR + lhi * 8) * 2;
    const unsigned aB_off = (l15 * TH_STR + lhi * 8) * 2;
    const unsigned bB_off = (l15 * WO_STR + lhi * 8) * 2;

    // ---- prologue: weights -> smem (once) ----
    for (int i = tid; i < 64 * 256; i += NTHR) {
        int n = i >> 8, c4 = i & 255;
        float4 v = ((const float4*)(w_r + (col0 + n) * NSTATE))[c4];
        __nv_bfloat16* d = wr_s + n * WR_STR + c4 * 4;
        d[0] = __float2bfloat16(v.x); d[1] = __float2bfloat16(v.y);
        d[2] = __float2bfloat16(v.z); d[3] = __float2bfloat16(v.w);
    }
    for (int i = tid; i < 16 * 256; i += NTHR) {
        int n = i >> 8, c4 = i & 255;
        float4 v = ((const float4*)(w_o + (nb2 + n) * NSTATE))[c4];
        __nv_bfloat16* d = wo_s + n * WO_STR + c4 * 4;
        d[0] = __float2bfloat16(v.x); d[1] = __float2bfloat16(v.y);
        d[2] = __float2bfloat16(v.z); d[3] = __float2bfloat16(v.w);
    }

    float br[4] = { b_r[cb], b_r[cb + 1], b_r[cb + 8], b_r[cb + 9] };
    const float bo = b_o[nb2 + (tid & 15)];
    float h[8];
    h[0] = h_init[r0 * NSTATE + cb];     h[1] = h_init[r0 * NSTATE + cb + 1];
    h[2] = h_init[r1 * NSTATE + cb];     h[3] = h_init[r1 * NSTATE + cb + 1];
    h[4] = h_init[r0 * NSTATE + cb + 8]; h[5] = h_init[r0 * NSTATE + cb + 9];
    h[6] = h_init[r1 * NSTATE + cb + 8]; h[7] = h_init[r1 * NSTATE + cb + 9];

    // publish tanh(h0) into th[0]
    stcg_u32(&g_th[0][r0 * NSTATE + cb],     pack2(tanh_f(h[0]), tanh_f(h[1])));
    stcg_u32(&g_th[0][r1 * NSTATE + cb],     pack2(tanh_f(h[2]), tanh_f(h[3])));
    stcg_u32(&g_th[0][r0 * NSTATE + cb + 8], pack2(tanh_f(h[4]), tanh_f(h[5])));
    stcg_u32(&g_th[0][r1 * NSTATE + cb + 8], pack2(tanh_f(h[6]), tanh_f(h[7])));

    if (tid == 0) {
        *s_base = g_flags[cta * 32];
        mbar_init(mb_u32, 1);
        mbar_init(mb_u32 + 8, 1);
    }
    __syncthreads();
    const unsigned base = *s_base;
    unsigned bar = 1;
    unsigned ph0 = 0, ph1 = 0;

    gbar(cta, grp, base + bar); bar++;

    // issue chunk0 of iteration 0 (reads th[0])
    if (wid == 0) {
        if (lane == 0) mbar_expect_tx(mb_u32, CHUNK_BYTES);
        __syncwarp();
        bulk_ldg(th_u32 + lane * (TH_STR * 2),
                 g_th[0] + (row0 + lane) * NSTATE, 512, mb_u32);
    }

    // ---- fused scan: iteration i loads tanh(h_i); C -> h_{i+1}; D -> err_{i-1} ----
    for (int i = 0; i <= SEQ; i++) {
        const __nv_bfloat16* thc = g_th[i & 1];
        const bool doC = (i < SEQ);
        const bool doD = (i > 0);

        float C0[4] = {0,0,0,0}, C1[4] = {0,0,0,0};
        float D[4][4];
        #pragma unroll
        for (int q = 0; q < 4; q++) { D[q][0]=0; D[q][1]=0; D[q][2]=0; D[q][3]=0; }

        // prefetch x for the epilogue (off critical path)
        float xv0 = 0.f, xv1 = 0.f; int oi0 = 0, oi1 = 0;
        if (doD) {
            const int t = i - 1;
            oi0 = (t * NBATCH + row0 + (tid >> 4)) * NOUT + nb2 + (tid & 15);
            oi1 = oi0 + 16 * NOUT;     // tid+256 -> row +16, same col
            xv0 = __ldg(x + oi0);
            xv1 = __ldg(x + oi1);
        }

        for (int ch = 0; ch < 4; ch++) {
            const unsigned mb = mb_u32 + (ch & 1) * 8;
            unsigned& ph = (ch & 1) ? ph1 : ph0;
            mbar_wait(mb, ph); ph ^= 1;

            if (ch < 3) {   // issue next chunk into the other half
                if (wid == 0) {
                    const unsigned mbn = mb_u32 + ((ch + 1) & 1) * 8;
                    if (lane == 0) mbar_expect_tx(mbn, CHUNK_BYTES);
                    __syncwarp();
                    bulk_ldg(th_u32 + ((ch + 1) & 1) * HALF_B + lane * (TH_STR * 2),
                             thc + (row0 + lane) * NSTATE + (ch + 1) * 256, 512, mbn);
                }
            }

            const unsigned cur = th_u32 + (ch & 1) * HALF_B;
            if (doC) {
                const unsigned abase = cur + aA_off;
                const unsigned bbase = wr_u32 + bA_off + ch * 512;
                #pragma unroll
                for (int kk = 0; kk < 16; kk++) {
                    unsigned a[4], b[4];
                    ldsm4(a, abase + kk * 32);
                    ldsm4(b, bbase + kk * 32);
                    unsigned b0[2] = { b[0], b[2] }, b1[2] = { b[1], b[3] };
                    mma16816(C0, a, b0);
                    mma16816(C1, a, b1);
                }
            }
            if (doD) {
                #pragma unroll
                for (int kk = 0; kk < 2; kk++) {
                    const int kl = wid * 32 + kk * 16;
                    unsigned a0[4], a1[4], b[4];
                    ldsm4(a0, cur + aB_off + kl * 2);
                    ldsm4(a1, cur + aB_off + kl * 2 + 16 * TH_STR * 2);
                    ldsm4(b, wo_u32 + bB_off + (ch * 256 + kl) * 2);
                    unsigned b0[2] = { b[0], b[2] }, b1[2] = { b[1], b[3] };
                    mma16816(D[0], a0, b0);
                    mma16816(D[1], a0, b1);
                    mma16816(D[2], a1, b0);
                    mma16816(D[3], a1, b1);
                }
            }
            __syncthreads();
        }

        if (doC) {
            #pragma unroll
            for (int j = 0; j < 4; j++) {
                h[j]     = OMALPHA * h[j]     + ALPHA * (C0[j] + br[j & 1]);
                h[4 + j] = OMALPHA * h[4 + j] + ALPHA * (C1[j] + br[2 + (j & 1)]);
            }
            __nv_bfloat16* thw = g_th[(i + 1) & 1];
            stcg_u32(&thw[r0 * NSTATE + cb],     pack2(tanh_f(h[0]), tanh_f(h[1])));
            stcg_u32(&thw[r1 * NSTATE + cb],     pack2(tanh_f(h[2]), tanh_f(h[3])));
            stcg_u32(&thw[r0 * NSTATE + cb + 8], pack2(tanh_f(h[4]), tanh_f(h[5])));
            stcg_u32(&thw[r1 * NSTATE + cb + 8], pack2(tanh_f(h[6]), tanh_f(h[7])));

            gbar(cta, grp, base + bar); bar++;

            // issue chunk0 of next iteration immediately (critical path)
            if (wid == 0) {
                if (lane == 0) mbar_expect_tx(mb_u32, CHUNK_BYTES);
                __syncwarp();
                bulk_ldg(th_u32 + lane * (TH_STR * 2),
                         thw + (row0 + lane) * NSTATE, 512, mb_u32);
            }
        }

        if (doD) {   // epilogue for err_{i-1}, off the inter-CTA critical path
            float* rw = red + wid * 512;
            #pragma unroll
            for (int q = 0; q < 4; q++) {
                int mi = q >> 1, ni = q & 1;
                #pragma unroll
                for (int j = 0; j < 4; j++) {
                    int rl = mi * 16 + g + ((j >> 1) << 3);
                    int cl = ni * 8 + 2 * tg + (j & 1);
                    rw[rl * 16 + cl] = D[q][j];
                }
            }
            __syncthreads();
            float s0 = 0.f, s1 = 0.f;
            #pragma unroll
            for (int w = 0; w < 8; w++) {
                s0 += red[w * 512 + tid];
                s1 += red[w * 512 + tid + 256];
            }
            out[oi0] = s0 + bo - xv0;
            out[oi1] = s1 + bo - xv1;
        }
    }
}

extern "C" void kernel_launch(void* const* d_in, const int* in_sizes, int n_in,
                              void* d_out, int out_size) {
    const float* x      = (const float*)d_in[0];
    const float* h_init = (const float*)d_in[1];
    const float* w_r    = (const float*)d_in[2];
    const float* b_r    = (const float*)d_in[3];
    const float* w_o    = (const float*)d_in[4];
    const float* b_o    = (const float*)d_in[5];
    float* out = (float*)d_out;

    static bool configured = false;
    if (!configured) {
        cudaFuncSetAttribute(rnn_scan_kernel,
                             cudaFuncAttributeMaxDynamicSharedMemorySize, SMEM_BYTES);
        configured = true;
    }
    rnn_scan_kernel<<<NCTA, NTHR, SMEM_BYTES>>>(x, h_init, w_r, b_r, w_o, b_o, out);
}

// round 11
// speedup vs baseline: 1.9202x; 1.4074x over previous
#include <cuda_runtime.h>
#include <cuda_bf16.h>
#include <cstdint>

#define SEQ     512
#define NBATCH  256
#define NSTATE  1024
#define NOUT    256
#define ALPHA   0.1f
#define OMALPHA 0.9f

#define NCTA 128
#define NTHR 256
#define BM 32
#define BN 64

// smem strides in bf16 elems; stride*2 mod 128 = 16 -> conflict-free LDSM
#define WR_STR 1032
#define WO_STR 1032
#define TH_STR 264

#define SMEM_WR   (64 * WR_STR)          // bf16 elems
#define CH_ELEM   (32 * TH_STR)          // one chunk buffer
#define SMEM_TH   (4 * CH_ELEM)          // 4 resident chunks
#define SMEM_RED  (8 * 512)              // floats
#define SMEM_BYTES ((SMEM_WR + SMEM_TH) * 2 + SMEM_RED * 4 + 64)
#define CH_B      (CH_ELEM * 2)          // chunk bytes in smem
#define CHUNK_BYTES 16384                // 32 rows x 512B payload

__device__ __align__(16) __nv_bfloat16 g_th[2][NBATCH * NSTATE];
__device__ unsigned g_flags[NCTA * 32];  // one flag per 128B

__device__ __forceinline__ float tanh_f(float v) {
    float r; asm("tanh.approx.f32 %0, %1;" : "=f"(r) : "f"(v)); return r;
}
__device__ __forceinline__ unsigned pack2(float a, float b) {
    __nv_bfloat162 t = __floats2bfloat162_rn(a, b);
    return *reinterpret_cast<unsigned*>(&t);
}
__device__ __forceinline__ void stcg_u32(void* p, unsigned v) {
    asm volatile("st.global.cg.b32 [%0], %1;" :: "l"(p), "r"(v));
}
__device__ __forceinline__ void ldsm4(unsigned r[4], unsigned addr) {
    asm volatile("ldmatrix.sync.aligned.m8n8.x4.shared.b16 {%0,%1,%2,%3}, [%4];"
                 : "=r"(r[0]), "=r"(r[1]), "=r"(r[2]), "=r"(r[3]) : "r"(addr));
}
__device__ __forceinline__ void mma16816(float c[4], const unsigned a[4], const unsigned b[2]) {
    asm volatile(
        "mma.sync.aligned.m16n8k16.row.col.f32.bf16.bf16.f32 "
        "{%0,%1,%2,%3},{%4,%5,%6,%7},{%8,%9},{%0,%1,%2,%3};"
        : "+f"(c[0]), "+f"(c[1]), "+f"(c[2]), "+f"(c[3])
        : "r"(a[0]), "r"(a[1]), "r"(a[2]), "r"(a[3]), "r"(b[0]), "r"(b[1]));
}

__device__ __forceinline__ void mbar_init(unsigned mbar, unsigned count) {
    asm volatile("mbarrier.init.shared.b64 [%0], %1;" :: "r"(mbar), "r"(count));
}
__device__ __forceinline__ void mbar_expect_tx(unsigned mbar, unsigned bytes) {
    asm volatile("mbarrier.arrive.expect_tx.shared.b64 _, [%0], %1;"
                 :: "r"(mbar), "r"(bytes) : "memory");
}
__device__ __forceinline__ void mbar_wait(unsigned mbar, unsigned parity) {
    asm volatile(
        "{\n\t.reg .pred P1;\n\t"
        "LAB_W_%=:\n\t"
        "mbarrier.try_wait.parity.acquire.cta.shared::cta.b64 P1, [%0], %1, 0x989680;\n\t"
        "@P1 bra LAB_D_%=;\n\t"
        "bra LAB_W_%=;\n\t"
        "LAB_D_%=:\n\t}"
        :: "r"(mbar), "r"(parity) : "memory");
}
__device__ __forceinline__ void bulk_ldg(unsigned dst_smem, const void* src,
                                         unsigned bytes, unsigned mbar) {
    asm volatile(
        "cp.async.bulk.shared::cta.global.mbarrier::complete_tx::bytes [%0], [%1], %2, [%3];"
        :: "r"(dst_smem), "l"(src), "r"(bytes), "r"(mbar) : "memory");
}

// 16-CTA group barrier on monotone per-CTA counters (replay-safe).
// st.release.gpu after __syncthreads provides release of all threads' prior stores.
__device__ __forceinline__ void gbar(int cta, int grp, unsigned target) {
    __syncthreads();
    if (threadIdx.x == 0)
        asm volatile("st.release.gpu.global.b32 [%0], %1;"
                     :: "l"(g_flags + cta * 32), "r"(target) : "memory");
    if (threadIdx.x < 16) {
        unsigned v;
        const unsigned* f = g_flags + (grp * 16 + threadIdx.x) * 32;
        do {
            asm volatile("ld.acquire.gpu.global.b32 %0, [%1];"
                         : "=r"(v) : "l"(f) : "memory");
        } while (v < target);
    }
    __syncthreads();
}

__global__ void __launch_bounds__(NTHR, 1)
rnn_scan_kernel(const float* __restrict__ x, const float* __restrict__ h_init,
                const float* __restrict__ w_r, const float* __restrict__ b_r,
                const float* __restrict__ w_o, const float* __restrict__ b_o,
                float* __restrict__ out)
{
    extern __shared__ char smem_raw[];
    __nv_bfloat16* wr_s = (__nv_bfloat16*)smem_raw;
    __nv_bfloat16* th_s = wr_s + SMEM_WR;     // 4 chunk buffers (also w_o staging in prologue)
    float*         red  = (float*)(th_s + SMEM_TH);
    unsigned long long* mbars = (unsigned long long*)(red + SMEM_RED);  // 4 mbarriers
    unsigned*      s_base = (unsigned*)(mbars + 4);

    const int cta = blockIdx.x, tid = threadIdx.x;
    const int wid = tid >> 5, lane = tid & 31;
    const int g = lane >> 2, tg = lane & 3;
    const int grp = cta >> 4;

    const int row0 = grp * BM;
    const int col0 = (cta & 15) * BN;
    const int wm = (wid >> 2) * 16, wn = (wid & 3) * 16;
    const int r0 = row0 + wm + g, r1 = r0 + 8;
    const int cb = col0 + wn + 2 * tg;
    const int nb2 = (cta & 15) * 16;

    const unsigned th_u32 = (unsigned)__cvta_generic_to_shared(th_s);
    const unsigned wr_u32 = (unsigned)__cvta_generic_to_shared(wr_s);
    const unsigned mb_u32 = (unsigned)__cvta_generic_to_shared(mbars);
    const int l15 = lane & 15, lhi = lane >> 4;
    const unsigned aA_off = ((wm + l15) * TH_STR + lhi * 8) * 2;
    const unsigned bA_off = ((wn + l15) * WR_STR + lhi * 8) * 2;
    const unsigned aB_off = (l15 * TH_STR + lhi * 8) * 2;
    const unsigned bB_off = (l15 * WO_STR + lhi * 8) * 2;

    // ---- prologue: w_r -> smem (once) ----
    for (int i = tid; i < 64 * 256; i += NTHR) {
        int n = i >> 8, c4 = i & 255;
        float4 v = ((const float4*)(w_r + (col0 + n) * NSTATE))[c4];
        __nv_bfloat16* d = wr_s + n * WR_STR + c4 * 4;
        d[0] = __float2bfloat16(v.x); d[1] = __float2bfloat16(v.y);
        d[2] = __float2bfloat16(v.z); d[3] = __float2bfloat16(v.w);
    }
    // stage w_o in th_s temporarily, then pull fragments into registers
    for (int i = tid; i < 16 * 256; i += NTHR) {
        int n = i >> 8, c4 = i & 255;
        float4 v = ((const float4*)(w_o + (nb2 + n) * NSTATE))[c4];
        __nv_bfloat16* d = th_s + n * WO_STR + c4 * 4;
        d[0] = __float2bfloat16(v.x); d[1] = __float2bfloat16(v.y);
        d[2] = __float2bfloat16(v.z); d[3] = __float2bfloat16(v.w);
    }
    __syncthreads();
    unsigned bD[32];   // w_o fragments, resident for all 512 steps
    #pragma unroll
    for (int ch = 0; ch < 4; ch++)
        #pragma unroll
        for (int kk = 0; kk < 2; kk++) {
            const int kl = wid * 32 + kk * 16;
            ldsm4(&bD[(ch * 2 + kk) * 4], th_u32 + bB_off + (ch * 256 + kl) * 2);
        }
    __syncthreads();

    float br[4] = { b_r[cb], b_r[cb + 1], b_r[cb + 8], b_r[cb + 9] };
    const float bo = b_o[nb2 + (tid & 15)];
    float h[8];
    h[0] = h_init[r0 * NSTATE + cb];     h[1] = h_init[r0 * NSTATE + cb + 1];
    h[2] = h_init[r1 * NSTATE + cb];     h[3] = h_init[r1 * NSTATE + cb + 1];
    h[4] = h_init[r0 * NSTATE + cb + 8]; h[5] = h_init[r0 * NSTATE + cb + 9];
    h[6] = h_init[r1 * NSTATE + cb + 8]; h[7] = h_init[r1 * NSTATE + cb + 9];

    stcg_u32(&g_th[0][r0 * NSTATE + cb],     pack2(tanh_f(h[0]), tanh_f(h[1])));
    stcg_u32(&g_th[0][r1 * NSTATE + cb],     pack2(tanh_f(h[2]), tanh_f(h[3])));
    stcg_u32(&g_th[0][r0 * NSTATE + cb + 8], pack2(tanh_f(h[4]), tanh_f(h[5])));
    stcg_u32(&g_th[0][r1 * NSTATE + cb + 8], pack2(tanh_f(h[6]), tanh_f(h[7])));

    if (tid == 0) {
        *s_base = g_flags[cta * 32];
        mbar_init(mb_u32,      1);
        mbar_init(mb_u32 + 8,  1);
        mbar_init(mb_u32 + 16, 1);
        mbar_init(mb_u32 + 24, 1);
    }
    __syncthreads();
    const unsigned base = *s_base;
    unsigned bar = 1;
    unsigned par = 0;

    gbar(cta, grp, base + bar); bar++;

    // issue all 4 chunks of iteration 0 (reads th[0]); warps 0-3, one chunk each
    if (wid < 4) {
        const unsigned mb = mb_u32 + wid * 8;
        if (lane == 0) mbar_expect_tx(mb, CHUNK_BYTES);
        __syncwarp();
        bulk_ldg(th_u32 + wid * CH_B + lane * (TH_STR * 2),
                 g_th[0] + (row0 + lane) * NSTATE + wid * 256, 512, mb);
    }

    // ---- fused scan: iter i consumes tanh(h_i); C -> h_{i+1}; D -> err_{i-1} ----
    for (int i = 0; i <= SEQ; i++) {
        const bool doC = (i < SEQ);
        const bool doD = (i > 0);

        float C0[4] = {0,0,0,0}, C1[4] = {0,0,0,0};
        float D[4][4];
        #pragma unroll
        for (int q = 0; q < 4; q++) { D[q][0]=0; D[q][1]=0; D[q][2]=0; D[q][3]=0; }

        float xv0 = 0.f, xv1 = 0.f; int oi0 = 0, oi1 = 0;
        if (doD) {
            const int t = i - 1;
            oi0 = (t * NBATCH + row0 + (tid >> 4)) * NOUT + nb2 + (tid & 15);
            oi1 = oi0 + 16 * NOUT;
            xv0 = __ldg(x + oi0);
            xv1 = __ldg(x + oi1);
        }

        #pragma unroll
        for (int ch = 0; ch < 4; ch++) {
            mbar_wait(mb_u32 + ch * 8, par);
            const unsigned cur = th_u32 + ch * CH_B;
            if (doC) {
                const unsigned abase = cur + aA_off;
                const unsigned bbase = wr_u32 + bA_off + ch * 512;
                #pragma unroll
                for (int kk = 0; kk < 16; kk++) {
                    unsigned a[4], b[4];
                    ldsm4(a, abase + kk * 32);
                    ldsm4(b, bbase + kk * 32);
                    unsigned b0[2] = { b[0], b[2] }, b1[2] = { b[1], b[3] };
                    mma16816(C0, a, b0);
                    mma16816(C1, a, b1);
                }
            }
            if (doD) {
                #pragma unroll
                for (int kk = 0; kk < 2; kk++) {
                    const int kl = wid * 32 + kk * 16;
                    unsigned a0[4], a1[4];
                    ldsm4(a0, cur + aB_off + kl * 2);
                    ldsm4(a1, cur + aB_off + kl * 2 + 16 * TH_STR * 2);
                    const unsigned* b = &bD[(ch * 2 + kk) * 4];
                    unsigned b0[2] = { b[0], b[2] }, b1[2] = { b[1], b[3] };
                    mma16816(D[0], a0, b0);
                    mma16816(D[1], a0, b1);
                    mma16816(D[2], a1, b0);
                    mma16816(D[3], a1, b1);
                }
            }
        }
        par ^= 1;

        if (doC) {
            #pragma unroll
            for (int j = 0; j < 4; j++) {
                h[j]     = OMALPHA * h[j]     + ALPHA * (C0[j] + br[j & 1]);
                h[4 + j] = OMALPHA * h[4 + j] + ALPHA * (C1[j] + br[2 + (j & 1)]);
            }
            __nv_bfloat16* thw = g_th[(i + 1) & 1];
            stcg_u32(&thw[r0 * NSTATE + cb],     pack2(tanh_f(h[0]), tanh_f(h[1])));
            stcg_u32(&thw[r1 * NSTATE + cb],     pack2(tanh_f(h[2]), tanh_f(h[3])));
            stcg_u32(&thw[r0 * NSTATE + cb + 8], pack2(tanh_f(h[4]), tanh_f(h[5])));
            stcg_u32(&thw[r1 * NSTATE + cb + 8], pack2(tanh_f(h[6]), tanh_f(h[7])));

            gbar(cta, grp, base + bar); bar++;

            // issue ALL 4 chunks of the next iteration immediately (critical path)
            if (wid < 4) {
                const unsigned mb = mb_u32 + wid * 8;
                if (lane == 0) mbar_expect_tx(mb, CHUNK_BYTES);
                __syncwarp();
                bulk_ldg(th_u32 + wid * CH_B + lane * (TH_STR * 2),
                         thw + (row0 + lane) * NSTATE + wid * 256, 512, mb);
            }
        }

        if (doD) {   // epilogue for err_{i-1}; hides under next iteration's TMA latency
            float* rw = red + wid * 512;
            #pragma unroll
            for (int q = 0; q < 4; q++) {
                int mi = q >> 1, ni = q & 1;
                #pragma unroll
                for (int j = 0; j < 4; j++) {
                    int rl = mi * 16 + g + ((j >> 1) << 3);
                    int cl = ni * 8 + 2 * tg + (j & 1);
                    rw[rl * 16 + cl] = D[q][j];
                }
            }
            __syncthreads();
            float s0 = 0.f, s1 = 0.f;
            #pragma unroll
            for (int w = 0; w < 8; w++) {
                s0 += red[w * 512 + tid];
                s1 += red[w * 512 + tid + 256];
            }
            out[oi0] = s0 + bo - xv0;
            out[oi1] = s1 + bo - xv1;
        }
    }
}

extern "C" void kernel_launch(void* const* d_in, const int* in_sizes, int n_in,
                              void* d_out, int out_size) {
    const float* x      = (const float*)d_in[0];
    const float* h_init = (const float*)d_in[1];
    const float* w_r    = (const float*)d_in[2];
    const float* b_r    = (const float*)d_in[3];
    const float* w_o    = (const float*)d_in[4];
    const float* b_o    = (const float*)d_in[5];
    float* out = (float*)d_out;

    static bool configured = false;
    if (!configured) {
        cudaFuncSetAttribute(rnn_scan_kernel,
                             cudaFuncAttributeMaxDynamicSharedMemorySize, SMEM_BYTES);
        configured = true;
    }
    rnn_scan_kernel<<<NCTA, NTHR, SMEM_BYTES>>>(x, h_init, w_r, b_r, w_o, b_o, out);
}